// round 2
// baseline (speedup 1.0000x reference)
#include <cuda_runtime.h>
#include <math.h>

// Problem constants (fixed by the reference)
#define BB   16
#define CC   256
#define NN   16384          // H*W = 128*128
#define KK   64
#define TEMPF 20.0f
#define EPSF  1e-6f
#define EM_STEPS 3

#define NSPLIT 32           // N-split for GEMM2 partials
#define NBLK_N (NN/128)     // 128 n-blocks in GEMM1

// -------- scratch (no allocations allowed -> device globals) --------
__device__ float g_m   [BB*CC*KK];                 // prototypes m [B][C][K]
__device__ float g_mtmp[BB*CC*KK];                 // scaled m' before l2norm
__device__ float g_S   [BB*KK];                    // softmax column sums
__device__ float g_Spart[NBLK_N*BB*KK];            // per-nblock column-sum partials
__device__ float g_part[(size_t)BB*NSPLIT*CC*KK];  // GEMM2 split partials

// -------- init: broadcast mu to all batches --------
__global__ void k_init(const float* __restrict__ mu) {
    int idx = blockIdx.x * 256 + threadIdx.x;      // B*C*K = 262144
    g_m[idx] = mu[idx & (CC*KK - 1)];
}

// -------- GEMM1: z[b,n,k] = softmax_k( scale * sum_c x[b,c,n]*m[b,c,k] ) ----
// grid (N/128, B), 256 threads. Per-thread 8(n) x 4(k). Fused softmax + colsum.
// TEMP_ON: EM-loop steps use scale=TEMP and emit column-sum partials.
// !TEMP_ON: final assignment, scale=1, no partials (reference has NO temp there).
template<bool TEMP_ON>
__global__ void __launch_bounds__(256)
k_gemm1(const float* __restrict__ x, float* __restrict__ z) {
    __shared__ float4 xs4[16][32];   // [c][n/4] : 16 x 128 floats
    __shared__ float4 ms4[16][16];   // [c][k/4] : 16 x  64 floats

    const int b   = blockIdx.y;
    const int n0  = blockIdx.x * 128;
    const int tid = threadIdx.x;
    const int kt  = tid & 15;        // k-thread: covers k = kt*4 .. kt*4+3
    const int nt  = tid >> 4;        // n-thread: covers n = nt*8 .. nt*8+7

    const float* __restrict__ xb = x  + (size_t)b * CC * NN;
    const float* __restrict__ mb = g_m + b * CC * KK;

    float acc[8][4];
#pragma unroll
    for (int i = 0; i < 8; i++)
#pragma unroll
        for (int j = 0; j < 4; j++) acc[i][j] = 0.0f;

    for (int cc = 0; cc < CC; cc += 16) {
        // load x tile: 16 c-rows x 128 n (512 float4, 2 per thread)
#pragma unroll
        for (int l = 0; l < 2; l++) {
            int idx = l * 256 + tid;
            int r = idx >> 5, q = idx & 31;
            xs4[r][q] = *(const float4*)(xb + (size_t)(cc + r) * NN + n0 + q * 4);
        }
        // load m tile: 16 c-rows x 64 k (256 float4, 1 per thread)
        {
            int r = tid >> 4, q = tid & 15;
            ms4[r][q] = *(const float4*)(mb + (cc + r) * KK + q * 4);
        }
        __syncthreads();

#pragma unroll
        for (int c = 0; c < 16; c++) {
            float4 a0 = xs4[c][nt * 2];
            float4 a1 = xs4[c][nt * 2 + 1];
            float4 bv = ms4[c][kt];
            float a[8] = {a0.x, a0.y, a0.z, a0.w, a1.x, a1.y, a1.z, a1.w};
            float bb[4] = {bv.x, bv.y, bv.z, bv.w};
#pragma unroll
            for (int i = 0; i < 8; i++)
#pragma unroll
                for (int j = 0; j < 4; j++)
                    acc[i][j] += a[i] * bb[j];
        }
        __syncthreads();
    }

    // fused softmax over k (row = fixed n; 64 k spread over 16 kt-lanes x 4)
    float colsum[4] = {0.f, 0.f, 0.f, 0.f};
#pragma unroll
    for (int i = 0; i < 8; i++) {
        float mx = -1e30f;
#pragma unroll
        for (int j = 0; j < 4; j++) {
            if (TEMP_ON) acc[i][j] *= TEMPF;       // final assignment: scale = 1
            mx = fmaxf(mx, acc[i][j]);
        }
#pragma unroll
        for (int m = 8; m; m >>= 1)
            mx = fmaxf(mx, __shfl_xor_sync(0xffffffffu, mx, m));
        float s = 0.0f;
#pragma unroll
        for (int j = 0; j < 4; j++) {
            float e = __expf(acc[i][j] - mx);
            acc[i][j] = e;
            s += e;
        }
#pragma unroll
        for (int m = 8; m; m >>= 1)
            s += __shfl_xor_sync(0xffffffffu, s, m);
        float inv = 1.0f / s;
        float4 o;
        o.x = acc[i][0] * inv; o.y = acc[i][1] * inv;
        o.z = acc[i][2] * inv; o.w = acc[i][3] * inv;
        *(float4*)(z + ((size_t)(b * NN) + n0 + nt * 8 + i) * KK + kt * 4) = o;
        if (TEMP_ON) {
            colsum[0] += o.x; colsum[1] += o.y; colsum[2] += o.z; colsum[3] += o.w;
        }
    }

    if (TEMP_ON) {
        // deterministic per-block column-sum partial (reduce over 16 nt)
        float* red = (float*)xs4;                 // 16*64 floats, fits
        // all reads of xs4 finished before last __syncthreads above
#pragma unroll
        for (int j = 0; j < 4; j++) red[nt * 64 + kt * 4 + j] = colsum[j];
        __syncthreads();
        if (tid < 64) {
            float s = 0.0f;
#pragma unroll
            for (int r = 0; r < 16; r++) s += red[r * 64 + tid];
            g_Spart[(blockIdx.x * BB + b) * KK + tid] = s;
        }
    }
}

// -------- GEMM2 partials: part[b,split,c,k] = sum_{n in split} x[b,c,n]*z[b,n,k]
// grid (NSPLIT, C/128, B), 256 threads, per-thread 8(c) x 4(k).
__global__ void __launch_bounds__(256)
k_gemm2(const float* __restrict__ x, const float* __restrict__ z) {
    __shared__ __align__(16) float xs[16 * 132];  // [n][c] transposed, pad 132
    __shared__ float4 zs4[16][16];                // [n][k/4]

    const int split = blockIdx.x;
    const int c0    = blockIdx.y * 128;
    const int b     = blockIdx.z;
    const int tid   = threadIdx.x;
    const int kt    = tid & 15;     // k = kt*4..kt*4+3
    const int ct    = tid >> 4;     // c = c0 + ct*8 .. +7

    const float* __restrict__ xb = x + (size_t)b * CC * NN;
    const float* __restrict__ zb = z + (size_t)b * NN * KK;
    const int ns0 = split * (NN / NSPLIT);        // 512-wide n chunk

    float acc[8][4];
#pragma unroll
    for (int i = 0; i < 8; i++)
#pragma unroll
        for (int j = 0; j < 4; j++) acc[i][j] = 0.0f;

    for (int nn = ns0; nn < ns0 + (NN / NSPLIT); nn += 16) {
        // load x: 128 c-rows x 16 n, store transposed [n][c]
#pragma unroll
        for (int l = 0; l < 2; l++) {
            int idx = l * 256 + tid;
            int r = idx >> 2, q = idx & 3;        // r = c row, q = n float4
            float4 v = *(const float4*)(xb + (size_t)(c0 + r) * NN + nn + q * 4);
            xs[(q * 4 + 0) * 132 + r] = v.x;
            xs[(q * 4 + 1) * 132 + r] = v.y;
            xs[(q * 4 + 2) * 132 + r] = v.z;
            xs[(q * 4 + 3) * 132 + r] = v.w;
        }
        // load z: 16 n-rows x 64 k
        {
            int r = tid >> 4, q = tid & 15;
            zs4[r][q] = *(const float4*)(zb + (size_t)(nn + r) * KK + q * 4);
        }
        __syncthreads();

#pragma unroll
        for (int n = 0; n < 16; n++) {
            float4 a0 = *(const float4*)&xs[n * 132 + ct * 8];
            float4 a1 = *(const float4*)&xs[n * 132 + ct * 8 + 4];
            float4 bv = zs4[n][kt];
            float a[8] = {a0.x, a0.y, a0.z, a0.w, a1.x, a1.y, a1.z, a1.w};
            float bb[4] = {bv.x, bv.y, bv.z, bv.w};
#pragma unroll
            for (int i = 0; i < 8; i++)
#pragma unroll
                for (int j = 0; j < 4; j++)
                    acc[i][j] += a[i] * bb[j];
        }
        __syncthreads();
    }

    // write partials (unique slot per block -> deterministic, no atomics)
#pragma unroll
    for (int i = 0; i < 8; i++) {
        float4 o;
        o.x = acc[i][0]; o.y = acc[i][1]; o.z = acc[i][2]; o.w = acc[i][3];
        *(float4*)(g_part + (((size_t)(b * NSPLIT + split)) * CC + c0 + ct * 8 + i) * KK + kt * 4) = o;
    }
}

// -------- S[b,k] = sum over 128 n-blocks of Spart --------
__global__ void k_sumS() {
    int b = blockIdx.x, k = threadIdx.x;          // block 64
    float s = 0.0f;
    for (int r = 0; r < NBLK_N; r++) s += g_Spart[(r * BB + b) * KK + k];
    g_S[b * KK + k] = s;
}

// -------- m'[b,c,k] = (sum_splits part) / (EPS + S[b,k]) --------
__global__ void k_reduceScale() {
    int c = blockIdx.x, b = blockIdx.y, k = threadIdx.x;   // block 64
    float s = 0.0f;
    size_t base = (((size_t)(b * NSPLIT)) * CC + c) * KK + k;
#pragma unroll 4
    for (int sp = 0; sp < NSPLIT; sp++) s += g_part[base + (size_t)sp * CC * KK];
    g_mtmp[(b * CC + c) * KK + k] = s / (EPSF + g_S[b * KK + k]);
}

// -------- l2-normalize m over C --------
__global__ void k_l2norm() {
    int k = blockIdx.x, b = blockIdx.y, c = threadIdx.x;   // block 256
    float v = g_mtmp[(b * CC + c) * KK + k];
    float sq = v * v;
#pragma unroll
    for (int m = 16; m; m >>= 1) sq += __shfl_xor_sync(0xffffffffu, sq, m);
    __shared__ float red[8];
    if ((threadIdx.x & 31) == 0) red[threadIdx.x >> 5] = sq;
    __syncthreads();
    float total = 0.0f;
#pragma unroll
    for (int w = 0; w < 8; w++) total += red[w];
    g_m[(b * CC + c) * KK + k] = v / (EPSF + sqrtf(total));
}

// -------- launch --------
extern "C" void kernel_launch(void* const* d_in, const int* in_sizes, int n_in,
                              void* d_out, int out_size) {
    const float* x  = (const float*)d_in[0];
    const float* mu = (const float*)d_in[1];
    if (n_in >= 2 && in_sizes[0] < in_sizes[1]) {   // defensive input ordering
        const float* t = x; x = mu; mu = t;
    }
    float* z = (float*)d_out;                        // [B,N,K] doubles as z scratch

    k_init<<<(BB * CC * KK) / 256, 256>>>(mu);

    for (int s = 0; s < EM_STEPS; s++) {
        k_gemm1<true><<<dim3(NBLK_N, BB), 256>>>(x, z);
        k_gemm2<<<dim3(NSPLIT, CC / 128, BB), 256>>>(x, z);
        k_sumS<<<BB, KK>>>();
        k_reduceScale<<<dim3(CC, BB), KK>>>();
        k_l2norm<<<dim3(KK, BB), 256>>>();
    }
    // final soft assignment: NO temperature in the reference here
    k_gemm1<false><<<dim3(NBLK_N, BB), 256>>>(x, z);
}